// round 6
// baseline (speedup 1.0000x reference)
#include <cuda_runtime.h>
#include <cuda_bf16.h>

#define FEATS 128
#define KNBR 20

// =================== helpers ===================
__device__ __forceinline__ unsigned int smem_u32(const void* p) {
    unsigned int a;
    asm("{ .reg .u64 t; cvta.to.shared.u64 t, %1; cvt.u32.u64 %0, t; }"
        : "=r"(a) : "l"(p));
    return a;
}

__device__ __forceinline__ void ldsm4(unsigned int r[4], unsigned int addr) {
    asm volatile("ldmatrix.sync.aligned.m8n8.x4.shared.b16 {%0,%1,%2,%3}, [%4];"
                 : "=r"(r[0]), "=r"(r[1]), "=r"(r[2]), "=r"(r[3])
                 : "r"(addr));
}

__device__ __forceinline__ void mma16816(float c[4], const unsigned int a[4],
                                         unsigned int b0, unsigned int b1) {
    asm volatile(
        "mma.sync.aligned.m16n8k16.row.col.f32.bf16.bf16.f32 "
        "{%0,%1,%2,%3}, {%4,%5,%6,%7}, {%8,%9}, {%0,%1,%2,%3};"
        : "+f"(c[0]), "+f"(c[1]), "+f"(c[2]), "+f"(c[3])
        : "r"(a[0]), "r"(a[1]), "r"(a[2]), "r"(a[3]), "r"(b0), "r"(b1));
}

__device__ __forceinline__ unsigned int sw128(unsigned int b) {
    return b ^ ((b >> 3) & 0x70);
}
// [128 x 128] bf16 K-major tile = two 64-k planes of 16KB, 128B rows
__device__ __forceinline__ unsigned int tile_off(int row, int k) {
    return ((unsigned)(k >> 6) << 14) + ((unsigned)row << 7) + ((unsigned)(k & 63) << 1);
}

__device__ __forceinline__ unsigned long long pack4bf(float a, float b, float c, float d) {
    __nv_bfloat162 lo = __floats2bfloat162_rn(a, b);
    __nv_bfloat162 hi = __floats2bfloat162_rn(c, d);
    unsigned int ulo = *reinterpret_cast<unsigned int*>(&lo);
    unsigned int uhi = *reinterpret_cast<unsigned int*>(&hi);
    unsigned long long u;
    asm("mov.b64 %0, {%1, %2};" : "=l"(u) : "r"(ulo), "r"(uhi));
    return u;
}

// split a float2 (two consecutive k) into bf16x2 hi and lo fragment regs
__device__ __forceinline__ void splitfrag(float2 v, unsigned int& hi, unsigned int& lo) {
    __nv_bfloat162 h = __floats2bfloat162_rn(v.x, v.y);
    float hx = __bfloat162float(h.x);
    float hy = __bfloat162float(h.y);
    __nv_bfloat162 l = __floats2bfloat162_rn(v.x - hx, v.y - hy);
    hi = *reinterpret_cast<unsigned int*>(&h);
    lo = *reinterpret_cast<unsigned int*>(&l);
}

// named-barrier producer/consumer handshakes (id 1 = G full, id 2 = G empty)
#define BAR_FULL_ARRIVE()  asm volatile("bar.arrive 1, 512;" ::: "memory")
#define BAR_FULL_SYNC()    asm volatile("bar.sync 1, 512;"   ::: "memory")
#define BAR_EMPTY_ARRIVE() asm volatile("bar.arrive 2, 512;" ::: "memory")
#define BAR_EMPTY_SYNC()   asm volatile("bar.sync 2, 512;"   ::: "memory")
#define MEMBAR_CTA()       asm volatile("membar.cta;"        ::: "memory")

// =================== smem layout (dynamic) ===================
// [0]       weights: Wc_h, Wc_l, Wn_h, Wn_l (each 32KB, [n][k] K-major SW128)
// [131072]  G tile: hi 32KB, lo 32KB
#define SM_G 131072u
#define SM_TOTAL 196608

// ---------------- fused persistent kernel ----------------
__global__ __launch_bounds__(512, 1)
void fused_kernel(const float* __restrict__ X,
                  const int* __restrict__ nh_idx,
                  const int* __restrict__ int_idx,
                  const float* __restrict__ nh_e,
                  const float* __restrict__ int_e,
                  const float* __restrict__ Wvc,
                  const float* __restrict__ Wvn,
                  const float* __restrict__ bv,
                  float* __restrict__ out,
                  int n, int ntiles) {
    extern __shared__ char smem[];
    unsigned int sb = smem_u32(smem);
    const int tid = threadIdx.x;
    const int wid = tid >> 5;
    const int lane = tid & 31;

    // ---- prologue: all 512 threads convert weights to smem (4 planes) ----
    for (int m = 0; m < 2; m++) {
        const float* W = m ? Wvn : Wvc;
        char* bh = smem + m * 65536;
        char* bl = bh + 32768;
        for (int idx = tid; idx < 4096; idx += 512) {
            int k  = idx >> 5;
            int n4 = (idx & 31) << 2;
            float4 w = *reinterpret_cast<const float4*>(W + k * FEATS + n4);
            float wv[4] = {w.x, w.y, w.z, w.w};
#pragma unroll
            for (int i = 0; i < 4; i++) {
                __nv_bfloat16 h = __float2bfloat16(wv[i]);
                float hf = __bfloat162float(h);
                __nv_bfloat16 l = __float2bfloat16(wv[i] - hf);
                unsigned int off = sw128(tile_off(n4 + i, k));
                *reinterpret_cast<__nv_bfloat16*>(bh + off) = h;
                *reinterpret_cast<__nv_bfloat16*>(bl + off) = l;
            }
        }
    }
    __syncthreads();

    if (wid < 8) {
        // ================= PRODUCER: gather-aggregate G into smem =================
        const float4* verts4 = reinterpret_cast<const float4*>(X);
        int first = 1;
        for (int tile = blockIdx.x; tile < ntiles; tile += gridDim.x) {
            if (!first) BAR_EMPTY_SYNC();
            first = 0;
#pragma unroll 1
            for (int i = 0; i < 16; i++) {
                int nl = wid * 16 + i;          // local row 0..127
                int node = tile * 128 + nl;
                if (node >= n) node = n - 1;    // padded rows: harmless dup

                int   iA = -1, iB = -1;
                float eA = 0.f, eB = 0.f;
                if (lane < KNBR) {
                    int base = node * KNBR + lane;
                    iA = nh_idx[base];
                    eA = nh_e[base];
                    iB = int_idx[base];
                    eB = int_e[base];
                }
                int validB = __popc(__ballot_sync(0xffffffffu, (lane < KNBR) && (iB >= 0)));

                float4 acc = make_float4(0.f, 0.f, 0.f, 0.f);
#pragma unroll
                for (int j = 0; j < KNBR; j++) {
                    int   idx = __shfl_sync(0xffffffffu, iA, j);
                    float e   = __shfl_sync(0xffffffffu, eA, j);
                    float4 v  = __ldg(&verts4[idx * (FEATS / 4) + lane]);
                    acc.x = fmaf(e, v.x, acc.x);
                    acc.y = fmaf(e, v.y, acc.y);
                    acc.z = fmaf(e, v.z, acc.z);
                    acc.w = fmaf(e, v.w, acc.w);
                }
#pragma unroll
                for (int j = 0; j < KNBR; j++) {
                    int idx = __shfl_sync(0xffffffffu, iB, j);
                    if (idx >= 0) {
                        float e  = __shfl_sync(0xffffffffu, eB, j);
                        float4 v = __ldg(&verts4[idx * (FEATS / 4) + lane]);
                        acc.x = fmaf(e, v.x, acc.x);
                        acc.y = fmaf(e, v.y, acc.y);
                        acc.z = fmaf(e, v.z, acc.z);
                        acc.w = fmaf(e, v.w, acc.w);
                    }
                }
                float inv = 1.0f / (float)(KNBR + validB);
                float gv[4] = {acc.x * inv, acc.y * inv, acc.z * inv, acc.w * inv};
                float hf[4];
#pragma unroll
                for (int q = 0; q < 4; q++)
                    hf[q] = __bfloat162float(__float2bfloat16(gv[q]));
                unsigned int off = sw128(tile_off(nl, lane * 4));
                *reinterpret_cast<unsigned long long*>(smem + SM_G + off) =
                    pack4bf(hf[0], hf[1], hf[2], hf[3]);
                *reinterpret_cast<unsigned long long*>(smem + SM_G + 32768u + off) =
                    pack4bf(gv[0] - hf[0], gv[1] - hf[1], gv[2] - hf[2], gv[3] - hf[3]);
            }
            MEMBAR_CTA();
            BAR_FULL_ARRIVE();
        }
    } else {
        // ================= CONSUMER: dual 3-term HMMA GEMM =================
        const int cw = wid - 8;     // 0..7
        const int wm = cw & 1;      // 64-row half
        const int wn = cw >> 1;     // 32-col block (0..3)
        const int mIdx = lane >> 3;
        const int r8 = lane & 7;

        // ldmatrix base offsets (pure-XOR SW128 form)
        const int rowGA = wm * 64 + ((mIdx & 1) << 3) + r8;   // rb=0 base
        const unsigned int prowA =
            ((unsigned)rowGA << 7) ^ ((unsigned)r8 << 4) ^ (((unsigned)mIdx >> 1) << 4);
        const int rowB = wn * 32 + ((mIdx >> 1) << 3) + r8;
        const unsigned int prowB =
            ((unsigned)rowB << 7) ^ ((unsigned)r8 << 4) ^ (((unsigned)mIdx & 1) << 4);

        const unsigned int GH = sb + SM_G;
        const unsigned int GL = GH + 32768u;

        float2 biasj[4];
#pragma unroll
        for (int j = 0; j < 4; j++) {
            int c = wn * 32 + j * 8 + ((lane & 3) << 1);
            biasj[j].x = __ldg(bv + c);
            biasj[j].y = __ldg(bv + c + 1);
        }

        for (int tile = blockIdx.x; tile < ntiles; tile += gridDim.x) {
            float acc[4][4][4];
#pragma unroll
            for (int rb = 0; rb < 4; rb++)
#pragma unroll
                for (int cb = 0; cb < 4; cb++)
#pragma unroll
                    for (int q = 0; q < 4; q++) acc[rb][cb][q] = 0.f;

            // ---- V phase: A from gmem fp32 (split in regs), B = Wc planes ----
            {
                const unsigned int WH = sb;            // Wc_h
                const unsigned int WL = sb + 32768u;   // Wc_l
                const int rbase = tile * 128 + wm * 64 + (lane >> 2);
#pragma unroll
                for (int ks = 0; ks < 8; ks++) {
                    const unsigned int Kc =
                        (((unsigned)ks >> 2) << 14) | (((unsigned)ks & 3) << 5);
                    unsigned int bh[2][4], bl[2][4];
                    ldsm4(bh[0], WH + (prowB ^ Kc));
                    ldsm4(bh[1], WH + (prowB ^ 0x800u ^ Kc));
                    ldsm4(bl[0], WL + (prowB ^ Kc));
                    ldsm4(bl[1], WL + (prowB ^ 0x800u ^ Kc));

                    const int kb = ks * 16 + ((lane & 3) << 1);
                    unsigned int ah[4][4], al[4][4];
#pragma unroll
                    for (int rb = 0; rb < 4; rb++) {
                        int r0 = rbase + rb * 16;
                        int r1 = r0 + 8;
                        if (r0 >= n) r0 = n - 1;
                        if (r1 >= n) r1 = n - 1;
                        const float* p0 = X + (long long)r0 * FEATS + kb;
                        const float* p1 = X + (long long)r1 * FEATS + kb;
                        float2 v00 = *reinterpret_cast<const float2*>(p0);
                        float2 v10 = *reinterpret_cast<const float2*>(p1);
                        float2 v01 = *reinterpret_cast<const float2*>(p0 + 8);
                        float2 v11 = *reinterpret_cast<const float2*>(p1 + 8);
                        splitfrag(v00, ah[rb][0], al[rb][0]);
                        splitfrag(v10, ah[rb][1], al[rb][1]);
                        splitfrag(v01, ah[rb][2], al[rb][2]);
                        splitfrag(v11, ah[rb][3], al[rb][3]);
                    }
#pragma unroll
                    for (int rb = 0; rb < 4; rb++) {
#pragma unroll
                        for (int cb = 0; cb < 4; cb++) {
                            unsigned int b0h = bh[cb >> 1][(cb & 1) * 2];
                            unsigned int b1h = bh[cb >> 1][(cb & 1) * 2 + 1];
                            unsigned int b0l = bl[cb >> 1][(cb & 1) * 2];
                            unsigned int b1l = bl[cb >> 1][(cb & 1) * 2 + 1];
                            mma16816(acc[rb][cb], ah[rb], b0h, b1h);
                            mma16816(acc[rb][cb], ah[rb], b0l, b1l);
                            mma16816(acc[rb][cb], al[rb], b0h, b1h);
                        }
                    }
                }
            }

            // ---- G phase: A from smem G tile (ldmatrix), B = Wn planes ----
            BAR_FULL_SYNC();
            {
                const unsigned int WH = sb + 65536u;   // Wn_h
                const unsigned int WL = sb + 98304u;   // Wn_l
#pragma unroll
                for (int ks = 0; ks < 8; ks++) {
                    const unsigned int Kc =
                        (((unsigned)ks >> 2) << 14) | (((unsigned)ks & 3) << 5);
                    unsigned int bh[2][4], bl[2][4];
                    ldsm4(bh[0], WH + (prowB ^ Kc));
                    ldsm4(bh[1], WH + (prowB ^ 0x800u ^ Kc));
                    ldsm4(bl[0], WL + (prowB ^ Kc));
                    ldsm4(bl[1], WL + (prowB ^ 0x800u ^ Kc));

                    unsigned int ah[4][4], al[4][4];
#pragma unroll
                    for (int rb = 0; rb < 4; rb++) {
                        unsigned int ra = (prowA ^ ((unsigned)rb << 11)) ^ Kc;
                        ldsm4(ah[rb], GH + ra);
                        ldsm4(al[rb], GL + ra);
                    }
#pragma unroll
                    for (int rb = 0; rb < 4; rb++) {
#pragma unroll
                        for (int cb = 0; cb < 4; cb++) {
                            unsigned int b0h = bh[cb >> 1][(cb & 1) * 2];
                            unsigned int b1h = bh[cb >> 1][(cb & 1) * 2 + 1];
                            unsigned int b0l = bl[cb >> 1][(cb & 1) * 2];
                            unsigned int b1l = bl[cb >> 1][(cb & 1) * 2 + 1];
                            mma16816(acc[rb][cb], ah[rb], b0h, b1h);
                            mma16816(acc[rb][cb], ah[rb], b0l, b1l);
                            mma16816(acc[rb][cb], al[rb], b0h, b1h);
                        }
                    }
                }
            }
            BAR_EMPTY_ARRIVE();

            // ---- epilogue: bias + relu + store ----
            const int rbase = tile * 128 + wm * 64 + (lane >> 2);
#pragma unroll
            for (int rb = 0; rb < 4; rb++) {
                int r0 = rbase + rb * 16;
                int r1 = r0 + 8;
#pragma unroll
                for (int cb = 0; cb < 4; cb++) {
                    int col = wn * 32 + cb * 8 + ((lane & 3) << 1);
                    if (r0 < n) {
                        float2 o;
                        o.x = fmaxf(acc[rb][cb][0] + biasj[cb].x, 0.f);
                        o.y = fmaxf(acc[rb][cb][1] + biasj[cb].y, 0.f);
                        *reinterpret_cast<float2*>(out + (long long)r0 * FEATS + col) = o;
                    }
                    if (r1 < n) {
                        float2 o;
                        o.x = fmaxf(acc[rb][cb][2] + biasj[cb].x, 0.f);
                        o.y = fmaxf(acc[rb][cb][3] + biasj[cb].y, 0.f);
                        *reinterpret_cast<float2*>(out + (long long)r1 * FEATS + col) = o;
                    }
                }
            }
        }
    }
}

extern "C" void kernel_launch(void* const* d_in, const int* in_sizes, int n_in,
                              void* d_out, int out_size) {
    const float* vertices = (const float*)d_in[0];
    const int*   nh_idx   = (const int*)d_in[1];
    const int*   int_idx  = (const int*)d_in[2];
    const float* nh_e     = (const float*)d_in[3];
    const float* int_e    = (const float*)d_in[4];
    const float* Wvc      = (const float*)d_in[5];
    const float* Wvn      = (const float*)d_in[6];
    const float* bv       = (const float*)d_in[7];
    float* out = (float*)d_out;

    int n = in_sizes[0] / FEATS;  // 50000
    int ntiles = (n + 127) / 128;
    int grid = ntiles < 148 ? ntiles : 148;

    cudaFuncSetAttribute(fused_kernel, cudaFuncAttributeMaxDynamicSharedMemorySize, SM_TOTAL);
    fused_kernel<<<grid, 512, SM_TOTAL>>>(vertices, nh_idx, int_idx, nh_e, int_e,
                                          Wvc, Wvn, bv, out, n, ntiles);
}

// round 7
// speedup vs baseline: 1.7319x; 1.7319x over previous
#include <cuda_runtime.h>
#include <cuda_bf16.h>

#define FEATS 128
#define KNBR 20

// =================== helpers ===================
__device__ __forceinline__ unsigned int smem_u32(const void* p) {
    unsigned int a;
    asm("{ .reg .u64 t; cvta.to.shared.u64 t, %1; cvt.u32.u64 %0, t; }"
        : "=r"(a) : "l"(p));
    return a;
}

__device__ __forceinline__ void ldsm4(unsigned int r[4], unsigned int addr) {
    asm volatile("ldmatrix.sync.aligned.m8n8.x4.shared.b16 {%0,%1,%2,%3}, [%4];"
                 : "=r"(r[0]), "=r"(r[1]), "=r"(r[2]), "=r"(r[3])
                 : "r"(addr));
}

__device__ __forceinline__ void mma16816(float c[4], const unsigned int a[4],
                                         unsigned int b0, unsigned int b1) {
    asm volatile(
        "mma.sync.aligned.m16n8k16.row.col.f32.bf16.bf16.f32 "
        "{%0,%1,%2,%3}, {%4,%5,%6,%7}, {%8,%9}, {%0,%1,%2,%3};"
        : "+f"(c[0]), "+f"(c[1]), "+f"(c[2]), "+f"(c[3])
        : "r"(a[0]), "r"(a[1]), "r"(a[2]), "r"(a[3]), "r"(b0), "r"(b1));
}

__device__ __forceinline__ unsigned int sw128(unsigned int b) {
    return b ^ ((b >> 3) & 0x70);
}
// [128 x 128] bf16 K-major tile = two 64-k planes of 16KB, 128B rows
__device__ __forceinline__ unsigned int tile_off(int row, int k) {
    return ((unsigned)(k >> 6) << 14) + ((unsigned)row << 7) + ((unsigned)(k & 63) << 1);
}

__device__ __forceinline__ unsigned long long pack4bf(float a, float b, float c, float d) {
    __nv_bfloat162 lo = __floats2bfloat162_rn(a, b);
    __nv_bfloat162 hi = __floats2bfloat162_rn(c, d);
    unsigned int ulo = *reinterpret_cast<unsigned int*>(&lo);
    unsigned int uhi = *reinterpret_cast<unsigned int*>(&hi);
    unsigned long long u;
    asm("mov.b64 %0, {%1, %2};" : "=l"(u) : "r"(ulo), "r"(uhi));
    return u;
}

// split a float2 (two consecutive k) into bf16x2 hi and lo fragment regs
__device__ __forceinline__ void splitfrag(float2 v, unsigned int& hi, unsigned int& lo) {
    __nv_bfloat162 h = __floats2bfloat162_rn(v.x, v.y);
    float hx = __bfloat162float(h.x);
    float hy = __bfloat162float(h.y);
    __nv_bfloat162 l = __floats2bfloat162_rn(v.x - hx, v.y - hy);
    hi = *reinterpret_cast<unsigned int*>(&h);
    lo = *reinterpret_cast<unsigned int*>(&l);
}

// named barriers: id = 1+2*half (full), 2+2*half (empty); 256 threads each
__device__ __forceinline__ void bar_arrive(int id) {
    asm volatile("bar.arrive %0, 256;" :: "r"(id) : "memory");
}
__device__ __forceinline__ void bar_wait(int id) {
    asm volatile("bar.sync %0, 256;" :: "r"(id) : "memory");
}
#define MEMBAR_CTA() asm volatile("membar.cta;" ::: "memory")

// =================== smem layout (dynamic) ===================
// [0]       weights: Wc_h, Wc_l, Wn_h, Wn_l (each 32KB, [n][k] K-major SW128)
// [131072]  G tile: hi 32KB, lo 32KB (rows 0-63 = half0, 64-127 = half1)
#define SM_G 131072u
#define SM_TOTAL 196608

// ---------------- fused persistent kernel ----------------
__global__ __launch_bounds__(512, 1)
void fused_kernel(const float* __restrict__ X,
                  const int* __restrict__ nh_idx,
                  const int* __restrict__ int_idx,
                  const float* __restrict__ nh_e,
                  const float* __restrict__ int_e,
                  const float* __restrict__ Wvc,
                  const float* __restrict__ Wvn,
                  const float* __restrict__ bv,
                  float* __restrict__ out,
                  int n, int ntiles) {
    extern __shared__ char smem[];
    unsigned int sb = smem_u32(smem);
    const int tid = threadIdx.x;
    const int wid = tid >> 5;
    const int lane = tid & 31;

    // ---- prologue: all 512 threads convert weights to smem (4 planes) ----
    for (int m = 0; m < 2; m++) {
        const float* W = m ? Wvn : Wvc;
        char* bh = smem + m * 65536;
        char* bl = bh + 32768;
        for (int idx = tid; idx < 4096; idx += 512) {
            int k  = idx >> 5;
            int n4 = (idx & 31) << 2;
            float4 w = *reinterpret_cast<const float4*>(W + k * FEATS + n4);
            float wv[4] = {w.x, w.y, w.z, w.w};
#pragma unroll
            for (int i = 0; i < 4; i++) {
                __nv_bfloat16 h = __float2bfloat16(wv[i]);
                float hf = __bfloat162float(h);
                __nv_bfloat16 l = __float2bfloat16(wv[i] - hf);
                unsigned int off = sw128(tile_off(n4 + i, k));
                *reinterpret_cast<__nv_bfloat16*>(bh + off) = h;
                *reinterpret_cast<__nv_bfloat16*>(bl + off) = l;
            }
        }
    }
    __syncthreads();

    if (wid < 8) {
        // ========== PRODUCER: shfl-free gather-aggregate into smem G ==========
        const float4* verts4 = reinterpret_cast<const float4*>(X);
        const int half = wid >> 2;            // warps 0-3: rows 0-63; 4-7: 64-127
        const int FULL = 1 + half * 2;
        const int EMPTY = 2 + half * 2;
        int first = 1;
        for (int tile = blockIdx.x; tile < ntiles; tile += gridDim.x) {
            if (!first) bar_wait(EMPTY);
            first = 0;
#pragma unroll 1
            for (int i = 0; i < 16; i++) {
                const int nl = wid * 16 + i;       // local row 0..127
                int node = tile * 128 + nl;
                if (node >= n) node = n - 1;

                // lane-uniform broadcast loads of all indices/edges (16B aligned)
                int ia[KNBR], ib[KNBR];
                float ea[KNBR], eb[KNBR];
                const int4*   piA = reinterpret_cast<const int4*>(nh_idx + node * KNBR);
                const int4*   piB = reinterpret_cast<const int4*>(int_idx + node * KNBR);
                const float4* peA = reinterpret_cast<const float4*>(nh_e + node * KNBR);
                const float4* peB = reinterpret_cast<const float4*>(int_e + node * KNBR);
#pragma unroll
                for (int q = 0; q < 5; q++) {
                    int4 a = __ldg(piA + q);
                    ia[q*4] = a.x; ia[q*4+1] = a.y; ia[q*4+2] = a.z; ia[q*4+3] = a.w;
                    int4 b = __ldg(piB + q);
                    ib[q*4] = b.x; ib[q*4+1] = b.y; ib[q*4+2] = b.z; ib[q*4+3] = b.w;
                    float4 x = __ldg(peA + q);
                    ea[q*4] = x.x; ea[q*4+1] = x.y; ea[q*4+2] = x.z; ea[q*4+3] = x.w;
                    float4 y = __ldg(peB + q);
                    eb[q*4] = y.x; eb[q*4+1] = y.y; eb[q*4+2] = y.z; eb[q*4+3] = y.w;
                }
                int validB = 0;
#pragma unroll
                for (int j = 0; j < KNBR; j++) validB += (ib[j] >= 0);

                float4 acc = make_float4(0.f, 0.f, 0.f, 0.f);
#pragma unroll
                for (int j = 0; j < KNBR; j++) {
                    float4 v = __ldg(&verts4[ia[j] * (FEATS / 4) + lane]);
                    float e = ea[j];
                    acc.x = fmaf(e, v.x, acc.x);
                    acc.y = fmaf(e, v.y, acc.y);
                    acc.z = fmaf(e, v.z, acc.z);
                    acc.w = fmaf(e, v.w, acc.w);
                }
#pragma unroll
                for (int j = 0; j < KNBR; j++) {
                    bool ok = (ib[j] >= 0);
                    int idx = ok ? ib[j] : ia[j];   // fallback row is L1-hot
                    float e = ok ? eb[j] : 0.f;
                    float4 v = __ldg(&verts4[idx * (FEATS / 4) + lane]);
                    acc.x = fmaf(e, v.x, acc.x);
                    acc.y = fmaf(e, v.y, acc.y);
                    acc.z = fmaf(e, v.z, acc.z);
                    acc.w = fmaf(e, v.w, acc.w);
                }
                float inv = 1.0f / (float)(KNBR + validB);
                float gv[4] = {acc.x * inv, acc.y * inv, acc.z * inv, acc.w * inv};
                float hf[4];
#pragma unroll
                for (int q = 0; q < 4; q++)
                    hf[q] = __bfloat162float(__float2bfloat16(gv[q]));
                unsigned int off = sw128(tile_off(nl, lane * 4));
                *reinterpret_cast<unsigned long long*>(smem + SM_G + off) =
                    pack4bf(hf[0], hf[1], hf[2], hf[3]);
                *reinterpret_cast<unsigned long long*>(smem + SM_G + 32768u + off) =
                    pack4bf(gv[0] - hf[0], gv[1] - hf[1], gv[2] - hf[2], gv[3] - hf[3]);
            }
            MEMBAR_CTA();
            bar_arrive(FULL);
        }
    } else {
        // ========== CONSUMER: dual 3-term HMMA GEMM (64x32 warp tiles) ==========
        const int cw = wid - 8;     // 0..7
        const int wm = cw & 1;      // 64-row half
        const int wn = cw >> 1;     // 32-col block (0..3)
        const int FULL = 1 + wm * 2;
        const int EMPTY = 2 + wm * 2;
        const int mIdx = lane >> 3;
        const int r8 = lane & 7;

        const int rowGA = wm * 64 + ((mIdx & 1) << 3) + r8;
        const unsigned int prowA =
            ((unsigned)rowGA << 7) ^ ((unsigned)r8 << 4) ^ (((unsigned)mIdx >> 1) << 4);
        const int rowB = wn * 32 + ((mIdx >> 1) << 3) + r8;
        const unsigned int prowB =
            ((unsigned)rowB << 7) ^ ((unsigned)r8 << 4) ^ (((unsigned)mIdx & 1) << 4);

        const unsigned int GH = sb + SM_G;
        const unsigned int GL = GH + 32768u;

        float2 biasj[4];
#pragma unroll
        for (int j = 0; j < 4; j++) {
            int c = wn * 32 + j * 8 + ((lane & 3) << 1);
            biasj[j].x = __ldg(bv + c);
            biasj[j].y = __ldg(bv + c + 1);
        }

        for (int tile = blockIdx.x; tile < ntiles; tile += gridDim.x) {
            float acc[4][4][4];
#pragma unroll
            for (int rb = 0; rb < 4; rb++)
#pragma unroll
                for (int cb = 0; cb < 4; cb++)
#pragma unroll
                    for (int q = 0; q < 4; q++) acc[rb][cb][q] = 0.f;

            // ---- V phase: A from gmem fp32 (split in regs), B = Wc planes ----
            {
                const unsigned int WH = sb;            // Wc_h
                const unsigned int WL = sb + 32768u;   // Wc_l
                const int rbase = tile * 128 + wm * 64 + (lane >> 2);
#pragma unroll
                for (int ks = 0; ks < 8; ks++) {
                    const unsigned int Kc =
                        (((unsigned)ks >> 2) << 14) | (((unsigned)ks & 3) << 5);
                    unsigned int bh[2][4], bl[2][4];
                    ldsm4(bh[0], WH + (prowB ^ Kc));
                    ldsm4(bh[1], WH + (prowB ^ 0x800u ^ Kc));
                    ldsm4(bl[0], WL + (prowB ^ Kc));
                    ldsm4(bl[1], WL + (prowB ^ 0x800u ^ Kc));

                    const int kb = ks * 16 + ((lane & 3) << 1);
                    unsigned int ah[4][4], al[4][4];
#pragma unroll
                    for (int rb = 0; rb < 4; rb++) {
                        int r0 = rbase + rb * 16;
                        int r1 = r0 + 8;
                        if (r0 >= n) r0 = n - 1;
                        if (r1 >= n) r1 = n - 1;
                        const float* p0 = X + (long long)r0 * FEATS + kb;
                        const float* p1 = X + (long long)r1 * FEATS + kb;
                        float2 v00 = *reinterpret_cast<const float2*>(p0);
                        float2 v10 = *reinterpret_cast<const float2*>(p1);
                        float2 v01 = *reinterpret_cast<const float2*>(p0 + 8);
                        float2 v11 = *reinterpret_cast<const float2*>(p1 + 8);
                        splitfrag(v00, ah[rb][0], al[rb][0]);
                        splitfrag(v10, ah[rb][1], al[rb][1]);
                        splitfrag(v01, ah[rb][2], al[rb][2]);
                        splitfrag(v11, ah[rb][3], al[rb][3]);
                    }
#pragma unroll
                    for (int rb = 0; rb < 4; rb++) {
#pragma unroll
                        for (int cb = 0; cb < 4; cb++) {
                            unsigned int b0h = bh[cb >> 1][(cb & 1) * 2];
                            unsigned int b1h = bh[cb >> 1][(cb & 1) * 2 + 1];
                            unsigned int b0l = bl[cb >> 1][(cb & 1) * 2];
                            unsigned int b1l = bl[cb >> 1][(cb & 1) * 2 + 1];
                            mma16816(acc[rb][cb], ah[rb], b0h, b1h);
                            mma16816(acc[rb][cb], ah[rb], b0l, b1l);
                            mma16816(acc[rb][cb], al[rb], b0h, b1h);
                        }
                    }
                }
            }

            // ---- G phase: A from smem G tile (own 64-row half) ----
            bar_wait(FULL);
            {
                const unsigned int WH = sb + 65536u;   // Wn_h
                const unsigned int WL = sb + 98304u;   // Wn_l
#pragma unroll
                for (int ks = 0; ks < 8; ks++) {
                    const unsigned int Kc =
                        (((unsigned)ks >> 2) << 14) | (((unsigned)ks & 3) << 5);
                    unsigned int bh[2][4], bl[2][4];
                    ldsm4(bh[0], WH + (prowB ^ Kc));
                    ldsm4(bh[1], WH + (prowB ^ 0x800u ^ Kc));
                    ldsm4(bl[0], WL + (prowB ^ Kc));
                    ldsm4(bl[1], WL + (prowB ^ 0x800u ^ Kc));

                    unsigned int ah[4][4], al[4][4];
#pragma unroll
                    for (int rb = 0; rb < 4; rb++) {
                        unsigned int ra = (prowA ^ ((unsigned)rb << 11)) ^ Kc;
                        ldsm4(ah[rb], GH + ra);
                        ldsm4(al[rb], GL + ra);
                    }
#pragma unroll
                    for (int rb = 0; rb < 4; rb++) {
#pragma unroll
                        for (int cb = 0; cb < 4; cb++) {
                            unsigned int b0h = bh[cb >> 1][(cb & 1) * 2];
                            unsigned int b1h = bh[cb >> 1][(cb & 1) * 2 + 1];
                            unsigned int b0l = bl[cb >> 1][(cb & 1) * 2];
                            unsigned int b1l = bl[cb >> 1][(cb & 1) * 2 + 1];
                            mma16816(acc[rb][cb], ah[rb], b0h, b1h);
                            mma16816(acc[rb][cb], ah[rb], b0l, b1l);
                            mma16816(acc[rb][cb], al[rb], b0h, b1h);
                        }
                    }
                }
            }
            bar_arrive(EMPTY);

            // ---- epilogue: bias + relu + store ----
            const int rbase = tile * 128 + wm * 64 + (lane >> 2);
#pragma unroll
            for (int rb = 0; rb < 4; rb++) {
                int r0 = rbase + rb * 16;
                int r1 = r0 + 8;
#pragma unroll
                for (int cb = 0; cb < 4; cb++) {
                    int col = wn * 32 + cb * 8 + ((lane & 3) << 1);
                    if (r0 < n) {
                        float2 o;
                        o.x = fmaxf(acc[rb][cb][0] + biasj[cb].x, 0.f);
                        o.y = fmaxf(acc[rb][cb][1] + biasj[cb].y, 0.f);
                        *reinterpret_cast<float2*>(out + (long long)r0 * FEATS + col) = o;
                    }
                    if (r1 < n) {
                        float2 o;
                        o.x = fmaxf(acc[rb][cb][2] + biasj[cb].x, 0.f);
                        o.y = fmaxf(acc[rb][cb][3] + biasj[cb].y, 0.f);
                        *reinterpret_cast<float2*>(out + (long long)r1 * FEATS + col) = o;
                    }
                }
            }
        }
    }
}

extern "C" void kernel_launch(void* const* d_in, const int* in_sizes, int n_in,
                              void* d_out, int out_size) {
    const float* vertices = (const float*)d_in[0];
    const int*   nh_idx   = (const int*)d_in[1];
    const int*   int_idx  = (const int*)d_in[2];
    const float* nh_e     = (const float*)d_in[3];
    const float* int_e    = (const float*)d_in[4];
    const float* Wvc      = (const float*)d_in[5];
    const float* Wvn      = (const float*)d_in[6];
    const float* bv       = (const float*)d_in[7];
    float* out = (float*)d_out;

    int n = in_sizes[0] / FEATS;  // 50000
    int ntiles = (n + 127) / 128;
    int grid = ntiles < 148 ? ntiles : 148;

    cudaFuncSetAttribute(fused_kernel, cudaFuncAttributeMaxDynamicSharedMemorySize, SM_TOTAL);
    fused_kernel<<<grid, 512, SM_TOTAL>>>(vertices, nh_idx, int_idx, nh_e, int_e,
                                          Wvc, Wvn, bv, out, n, ntiles);
}

// round 8
// speedup vs baseline: 1.9083x; 1.1018x over previous
#include <cuda_runtime.h>
#include <cuda_bf16.h>

#define FEATS 128
#define KNBR 20

// =================== helpers ===================
__device__ __forceinline__ unsigned int smem_u32(const void* p) {
    unsigned int a;
    asm("{ .reg .u64 t; cvta.to.shared.u64 t, %1; cvt.u32.u64 %0, t; }"
        : "=r"(a) : "l"(p));
    return a;
}

__device__ __forceinline__ void ldsm4(unsigned int r[4], unsigned int addr) {
    asm volatile("ldmatrix.sync.aligned.m8n8.x4.shared.b16 {%0,%1,%2,%3}, [%4];"
                 : "=r"(r[0]), "=r"(r[1]), "=r"(r[2]), "=r"(r[3])
                 : "r"(addr));
}

__device__ __forceinline__ void mma16816(float c[4], const unsigned int a[4],
                                         unsigned int b0, unsigned int b1) {
    asm volatile(
        "mma.sync.aligned.m16n8k16.row.col.f32.bf16.bf16.f32 "
        "{%0,%1,%2,%3}, {%4,%5,%6,%7}, {%8,%9}, {%0,%1,%2,%3};"
        : "+f"(c[0]), "+f"(c[1]), "+f"(c[2]), "+f"(c[3])
        : "r"(a[0]), "r"(a[1]), "r"(a[2]), "r"(a[3]), "r"(b0), "r"(b1));
}

__device__ __forceinline__ unsigned int sw128(unsigned int b) {
    return b ^ ((b >> 3) & 0x70);
}
// [128 x 128] bf16 K-major tile = two 64-k planes of 16KB, 128B rows
__device__ __forceinline__ unsigned int tile_off(int row, int k) {
    return ((unsigned)(k >> 6) << 14) + ((unsigned)row << 7) + ((unsigned)(k & 63) << 1);
}

__device__ __forceinline__ unsigned long long pack4bf(float a, float b, float c, float d) {
    __nv_bfloat162 lo = __floats2bfloat162_rn(a, b);
    __nv_bfloat162 hi = __floats2bfloat162_rn(c, d);
    unsigned int ulo = *reinterpret_cast<unsigned int*>(&lo);
    unsigned int uhi = *reinterpret_cast<unsigned int*>(&hi);
    unsigned long long u;
    asm("mov.b64 %0, {%1, %2};" : "=l"(u) : "r"(ulo), "r"(uhi));
    return u;
}

// split a float2 (two consecutive k) into bf16x2 hi and lo fragment regs
__device__ __forceinline__ void splitfrag(float2 v, unsigned int& hi, unsigned int& lo) {
    __nv_bfloat162 h = __floats2bfloat162_rn(v.x, v.y);
    float hx = __bfloat162float(h.x);
    float hy = __bfloat162float(h.y);
    __nv_bfloat162 l = __floats2bfloat162_rn(v.x - hx, v.y - hy);
    hi = *reinterpret_cast<unsigned int*>(&h);
    lo = *reinterpret_cast<unsigned int*>(&l);
}

__device__ __forceinline__ void fma4(float4& acc, float e, float4 v) {
    acc.x = fmaf(e, v.x, acc.x);
    acc.y = fmaf(e, v.y, acc.y);
    acc.z = fmaf(e, v.z, acc.z);
    acc.w = fmaf(e, v.w, acc.w);
}

// named barriers: id = 1+2*half (full), 2+2*half (empty); 256 threads each
__device__ __forceinline__ void bar_arrive(int id) {
    asm volatile("bar.arrive %0, 256;" :: "r"(id) : "memory");
}
__device__ __forceinline__ void bar_wait(int id) {
    asm volatile("bar.sync %0, 256;" :: "r"(id) : "memory");
}
#define MEMBAR_CTA() asm volatile("membar.cta;" ::: "memory")

// =================== smem layout (dynamic) ===================
// [0]       weights: Wc_h, Wc_l, Wn_h, Wn_l (each 32KB, [n][k] K-major SW128)
// [131072]  G tile: hi 32KB, lo 32KB (rows 0-63 = half0, 64-127 = half1)
#define SM_G 131072u
#define SM_TOTAL 196608

// ---------------- fused persistent kernel ----------------
__global__ __launch_bounds__(512, 1)
void fused_kernel(const float* __restrict__ X,
                  const int* __restrict__ nh_idx,
                  const int* __restrict__ int_idx,
                  const float* __restrict__ nh_e,
                  const float* __restrict__ int_e,
                  const float* __restrict__ Wvc,
                  const float* __restrict__ Wvn,
                  const float* __restrict__ bv,
                  float* __restrict__ out,
                  int n, int ntiles) {
    extern __shared__ char smem[];
    unsigned int sb = smem_u32(smem);
    const int tid = threadIdx.x;
    const int wid = tid >> 5;
    const int lane = tid & 31;

    // ---- prologue: all 512 threads convert weights to smem (4 planes) ----
    for (int m = 0; m < 2; m++) {
        const float* W = m ? Wvn : Wvc;
        char* bh = smem + m * 65536;
        char* bl = bh + 32768;
        for (int idx = tid; idx < 4096; idx += 512) {
            int k  = idx >> 5;
            int n4 = (idx & 31) << 2;
            float4 w = *reinterpret_cast<const float4*>(W + k * FEATS + n4);
            float wv[4] = {w.x, w.y, w.z, w.w};
#pragma unroll
            for (int i = 0; i < 4; i++) {
                __nv_bfloat16 h = __float2bfloat16(wv[i]);
                float hf = __bfloat162float(h);
                __nv_bfloat16 l = __float2bfloat16(wv[i] - hf);
                unsigned int off = sw128(tile_off(n4 + i, k));
                *reinterpret_cast<__nv_bfloat16*>(bh + off) = h;
                *reinterpret_cast<__nv_bfloat16*>(bl + off) = l;
            }
        }
    }
    __syncthreads();

    if (wid < 8) {
        // ========== PRODUCER: chunked gather-aggregate into smem G ==========
        const float4* verts4 = reinterpret_cast<const float4*>(X);
        const int half = wid >> 2;            // warps 0-3: rows 0-63; 4-7: 64-127
        const int FULL = 1 + half * 2;
        const int EMPTY = 2 + half * 2;
        int first = 1;
        for (int tile = blockIdx.x; tile < ntiles; tile += gridDim.x) {
            if (!first) bar_wait(EMPTY);
            first = 0;
#pragma unroll 1
            for (int i = 0; i < 16; i++) {
                const int nl = wid * 16 + i;       // local row 0..127
                int node = tile * 128 + nl;
                if (node >= n) node = n - 1;

                const int4*   piA = reinterpret_cast<const int4*>(nh_idx + node * KNBR);
                const int4*   piB = reinterpret_cast<const int4*>(int_idx + node * KNBR);
                const float4* peA = reinterpret_cast<const float4*>(nh_e + node * KNBR);
                const float4* peB = reinterpret_cast<const float4*>(int_e + node * KNBR);

                float4 acc = make_float4(0.f, 0.f, 0.f, 0.f);
                int validB = 0;

                // neighborhood: always valid, chunked 4-at-a-time
#pragma unroll
                for (int q = 0; q < 5; q++) {
                    int4   a = __ldg(piA + q);
                    float4 e = __ldg(peA + q);
                    float4 v0 = __ldg(&verts4[a.x * 32 + lane]);
                    float4 v1 = __ldg(&verts4[a.y * 32 + lane]);
                    float4 v2 = __ldg(&verts4[a.z * 32 + lane]);
                    float4 v3 = __ldg(&verts4[a.w * 32 + lane]);
                    fma4(acc, e.x, v0);
                    fma4(acc, e.y, v1);
                    fma4(acc, e.z, v2);
                    fma4(acc, e.w, v3);
                }
                // interface: warp-uniform validity (skip saves L2 bytes)
#pragma unroll
                for (int q = 0; q < 5; q++) {
                    int4   b = __ldg(piB + q);
                    float4 e = __ldg(peB + q);
                    if (b.x >= 0) { fma4(acc, e.x, __ldg(&verts4[b.x * 32 + lane])); validB++; }
                    if (b.y >= 0) { fma4(acc, e.y, __ldg(&verts4[b.y * 32 + lane])); validB++; }
                    if (b.z >= 0) { fma4(acc, e.z, __ldg(&verts4[b.z * 32 + lane])); validB++; }
                    if (b.w >= 0) { fma4(acc, e.w, __ldg(&verts4[b.w * 32 + lane])); validB++; }
                }
                float inv = 1.0f / (float)(KNBR + validB);
                float gv[4] = {acc.x * inv, acc.y * inv, acc.z * inv, acc.w * inv};
                float hf[4];
#pragma unroll
                for (int q = 0; q < 4; q++)
                    hf[q] = __bfloat162float(__float2bfloat16(gv[q]));
                unsigned int off = sw128(tile_off(nl, lane * 4));
                *reinterpret_cast<unsigned long long*>(smem + SM_G + off) =
                    pack4bf(hf[0], hf[1], hf[2], hf[3]);
                *reinterpret_cast<unsigned long long*>(smem + SM_G + 32768u + off) =
                    pack4bf(gv[0] - hf[0], gv[1] - hf[1], gv[2] - hf[2], gv[3] - hf[3]);
            }
            MEMBAR_CTA();
            bar_arrive(FULL);
        }
    } else {
        // ========== CONSUMER: dual 3-term HMMA GEMM (64x32 warp tiles) ==========
        const int cw = wid - 8;     // 0..7
        const int wm = cw & 1;      // 64-row half
        const int wn = cw >> 1;     // 32-col block (0..3)
        const int FULL = 1 + wm * 2;
        const int EMPTY = 2 + wm * 2;
        const int mIdx = lane >> 3;
        const int r8 = lane & 7;

        const int rowGA = wm * 64 + ((mIdx & 1) << 3) + r8;
        const unsigned int prowA =
            ((unsigned)rowGA << 7) ^ ((unsigned)r8 << 4) ^ (((unsigned)mIdx >> 1) << 4);
        const int rowB = wn * 32 + ((mIdx >> 1) << 3) + r8;
        const unsigned int prowB =
            ((unsigned)rowB << 7) ^ ((unsigned)r8 << 4) ^ (((unsigned)mIdx & 1) << 4);

        const unsigned int GH = sb + SM_G;
        const unsigned int GL = GH + 32768u;

        float2 biasj[4];
#pragma unroll
        for (int j = 0; j < 4; j++) {
            int c = wn * 32 + j * 8 + ((lane & 3) << 1);
            biasj[j].x = __ldg(bv + c);
            biasj[j].y = __ldg(bv + c + 1);
        }

        for (int tile = blockIdx.x; tile < ntiles; tile += gridDim.x) {
            float acc[4][4][4];
#pragma unroll
            for (int rb = 0; rb < 4; rb++)
#pragma unroll
                for (int cb = 0; cb < 4; cb++)
#pragma unroll
                    for (int q = 0; q < 4; q++) acc[rb][cb][q] = 0.f;

            // ---- V phase: A from gmem fp32 (split in regs), B = Wc planes ----
            {
                const unsigned int WH = sb;            // Wc_h
                const unsigned int WL = sb + 32768u;   // Wc_l
                const int rbase = tile * 128 + wm * 64 + (lane >> 2);
#pragma unroll
                for (int ks = 0; ks < 8; ks++) {
                    const unsigned int Kc =
                        (((unsigned)ks >> 2) << 14) | (((unsigned)ks & 3) << 5);
                    unsigned int bh[2][4], bl[2][4];
                    ldsm4(bh[0], WH + (prowB ^ Kc));
                    ldsm4(bh[1], WH + (prowB ^ 0x800u ^ Kc));
                    ldsm4(bl[0], WL + (prowB ^ Kc));
                    ldsm4(bl[1], WL + (prowB ^ 0x800u ^ Kc));

                    const int kb = ks * 16 + ((lane & 3) << 1);
                    unsigned int ah[4][4], al[4][4];
#pragma unroll
                    for (int rb = 0; rb < 4; rb++) {
                        int r0 = rbase + rb * 16;
                        int r1 = r0 + 8;
                        if (r0 >= n) r0 = n - 1;
                        if (r1 >= n) r1 = n - 1;
                        const float* p0 = X + (long long)r0 * FEATS + kb;
                        const float* p1 = X + (long long)r1 * FEATS + kb;
                        float2 v00 = *reinterpret_cast<const float2*>(p0);
                        float2 v10 = *reinterpret_cast<const float2*>(p1);
                        float2 v01 = *reinterpret_cast<const float2*>(p0 + 8);
                        float2 v11 = *reinterpret_cast<const float2*>(p1 + 8);
                        splitfrag(v00, ah[rb][0], al[rb][0]);
                        splitfrag(v10, ah[rb][1], al[rb][1]);
                        splitfrag(v01, ah[rb][2], al[rb][2]);
                        splitfrag(v11, ah[rb][3], al[rb][3]);
                    }
#pragma unroll
                    for (int rb = 0; rb < 4; rb++) {
#pragma unroll
                        for (int cb = 0; cb < 4; cb++) {
                            unsigned int b0h = bh[cb >> 1][(cb & 1) * 2];
                            unsigned int b1h = bh[cb >> 1][(cb & 1) * 2 + 1];
                            unsigned int b0l = bl[cb >> 1][(cb & 1) * 2];
                            unsigned int b1l = bl[cb >> 1][(cb & 1) * 2 + 1];
                            mma16816(acc[rb][cb], ah[rb], b0h, b1h);
                            mma16816(acc[rb][cb], ah[rb], b0l, b1l);
                            mma16816(acc[rb][cb], al[rb], b0h, b1h);
                        }
                    }
                }
            }

            // ---- G phase: A from smem G tile (own 64-row half) ----
            bar_wait(FULL);
            {
                const unsigned int WH = sb + 65536u;   // Wn_h
                const unsigned int WL = sb + 98304u;   // Wn_l
#pragma unroll
                for (int ks = 0; ks < 8; ks++) {
                    const unsigned int Kc =
                        (((unsigned)ks >> 2) << 14) | (((unsigned)ks & 3) << 5);
                    unsigned int bh[2][4], bl[2][4];
                    ldsm4(bh[0], WH + (prowB ^ Kc));
                    ldsm4(bh[1], WH + (prowB ^ 0x800u ^ Kc));
                    ldsm4(bl[0], WL + (prowB ^ Kc));
                    ldsm4(bl[1], WL + (prowB ^ 0x800u ^ Kc));

                    unsigned int ah[4][4], al[4][4];
#pragma unroll
                    for (int rb = 0; rb < 4; rb++) {
                        unsigned int ra = (prowA ^ ((unsigned)rb << 11)) ^ Kc;
                        ldsm4(ah[rb], GH + ra);
                        ldsm4(al[rb], GL + ra);
                    }
#pragma unroll
                    for (int rb = 0; rb < 4; rb++) {
#pragma unroll
                        for (int cb = 0; cb < 4; cb++) {
                            unsigned int b0h = bh[cb >> 1][(cb & 1) * 2];
                            unsigned int b1h = bh[cb >> 1][(cb & 1) * 2 + 1];
                            unsigned int b0l = bl[cb >> 1][(cb & 1) * 2];
                            unsigned int b1l = bl[cb >> 1][(cb & 1) * 2 + 1];
                            mma16816(acc[rb][cb], ah[rb], b0h, b1h);
                            mma16816(acc[rb][cb], ah[rb], b0l, b1l);
                            mma16816(acc[rb][cb], al[rb], b0h, b1h);
                        }
                    }
                }
            }
            bar_arrive(EMPTY);

            // ---- epilogue: bias + relu + store ----
            const int rbase = tile * 128 + wm * 64 + (lane >> 2);
#pragma unroll
            for (int rb = 0; rb < 4; rb++) {
                int r0 = rbase + rb * 16;
                int r1 = r0 + 8;
#pragma unroll
                for (int cb = 0; cb < 4; cb++) {
                    int col = wn * 32 + cb * 8 + ((lane & 3) << 1);
                    if (r0 < n) {
                        float2 o;
                        o.x = fmaxf(acc[rb][cb][0] + biasj[cb].x, 0.f);
                        o.y = fmaxf(acc[rb][cb][1] + biasj[cb].y, 0.f);
                        *reinterpret_cast<float2*>(out + (long long)r0 * FEATS + col) = o;
                    }
                    if (r1 < n) {
                        float2 o;
                        o.x = fmaxf(acc[rb][cb][2] + biasj[cb].x, 0.f);
                        o.y = fmaxf(acc[rb][cb][3] + biasj[cb].y, 0.f);
                        *reinterpret_cast<float2*>(out + (long long)r1 * FEATS + col) = o;
                    }
                }
            }
        }
    }
}

extern "C" void kernel_launch(void* const* d_in, const int* in_sizes, int n_in,
                              void* d_out, int out_size) {
    const float* vertices = (const float*)d_in[0];
    const int*   nh_idx   = (const int*)d_in[1];
    const int*   int_idx  = (const int*)d_in[2];
    const float* nh_e     = (const float*)d_in[3];
    const float* int_e    = (const float*)d_in[4];
    const float* Wvc      = (const float*)d_in[5];
    const float* Wvn      = (const float*)d_in[6];
    const float* bv       = (const float*)d_in[7];
    float* out = (float*)d_out;

    int n = in_sizes[0] / FEATS;  // 50000
    int ntiles = (n + 127) / 128;
    int grid = ntiles < 148 ? ntiles : 148;

    cudaFuncSetAttribute(fused_kernel, cudaFuncAttributeMaxDynamicSharedMemorySize, SM_TOTAL);
    fused_kernel<<<grid, 512, SM_TOTAL>>>(vertices, nh_idx, int_idx, nh_e, int_e,
                                          Wvc, Wvn, bv, out, n, ntiles);
}